// round 1
// baseline (speedup 1.0000x reference)
#include <cuda_runtime.h>
#include <math.h>

#define NB 4
#define NQ 2048
#define NKV 2048
#define NH 8
#define DQK 160
#define DV 288
#define DVP 320
#define SCALE 0.07905694150420949f  /* 1/sqrt(8*16+32) */

// ---------------- scratch (static device globals; no allocation) ----------------
__device__ __align__(128) float g_kfeat[NB][NKV][DQK];      //  5.2 MB
__device__ __align__(128) float g_vfeat[NB][NKV][DVP];      // 10.5 MB (288 used, padded)
__device__ __align__(128) float g_qfeat[NB][NH][NQ][DQK];   // 41.9 MB
__device__ __align__(128) float g_S[NB * NH][NQ][NKV];      // 512 MB (scores -> probs in place)
__device__ __align__(128) float g_att[NB][NH][NQ][DVP];     // 83.9 MB

// ---------------- PGA basis structure tables ----------------
// out[a] = sum_c w[c, YD[a]] * mv[c, a]  (+ w[c, Y2[a]] * mv[c, SRC[a]] if SRC[a] >= 0)
__constant__ int c_YD[16]   = {0,1,1,1,1,2,2,2,2,2,2,3,3,3,3,4};
__constant__ int c_Y2[16]   = {0,5,0,0,0,6,6,6,0,0,0,7,7,7,0,8};
__constant__ int c_SRC[16]  = {-1,0,-1,-1,-1,2,3,4,-1,-1,-1,8,9,10,-1,14};
__constant__ int c_INNER[8] = {0,2,3,4,8,9,10,14};

// ================= K/V projection =================
// grid = NB*NKV blocks, 256 threads. k_feat[c*8+xi] / v_feat[c*16+a] layouts.
__global__ __launch_bounds__(256) void kv_proj_kernel(
    const float* __restrict__ mv_kv, const float* __restrict__ s_kv,
    const float* __restrict__ kw_mv, const float* __restrict__ kw_s2mv, const float* __restrict__ kb_mv,
    const float* __restrict__ kw_mv2s, const float* __restrict__ kw_s2s, const float* __restrict__ kb_s,
    const float* __restrict__ vw_mv, const float* __restrict__ vw_s2mv, const float* __restrict__ vb_mv,
    const float* __restrict__ vw_mv2s, const float* __restrict__ vw_s2s, const float* __restrict__ vb_s)
{
    const int tok = blockIdx.x;
    const int b = tok / NKV, n = tok % NKV;
    __shared__ float smv[16][16];
    __shared__ float ss[32];
    const int tid = threadIdx.x;
    ((float*)smv)[tid] = mv_kv[(size_t)tok * 256 + tid];
    if (tid < 32) ss[tid] = s_kv[(size_t)tok * 32 + tid];
    __syncthreads();

    for (int j = tid; j < 480; j += 256) {
        float val = 0.f;
        if (j < 128) {                       // k_mv inner components
            const int c = j >> 3, xi = j & 7;
            const int a = c_INNER[xi], y = c_YD[a];
            const float* w = kw_mv + (c * 16) * 9 + y;
            #pragma unroll
            for (int ci = 0; ci < 16; ci++) val += w[ci * 9] * smv[ci][a];
            if (a == 0) {
                #pragma unroll
                for (int i = 0; i < 32; i++) val += ss[i] * kw_s2mv[c * 32 + i];
                val += kb_mv[c];
            }
            g_kfeat[b][n][j] = val;
        } else if (j < 160) {                // k scalars
            const int cs = j - 128;
            #pragma unroll
            for (int ci = 0; ci < 16; ci++) val += smv[ci][0] * kw_mv2s[cs * 16 + ci];
            #pragma unroll
            for (int i = 0; i < 32; i++) val += ss[i] * kw_s2s[cs * 32 + i];
            g_kfeat[b][n][j] = val + kb_s[cs];
        } else if (j < 416) {                // v_mv, all 16 components
            const int j2 = j - 160;
            const int c = j2 >> 4, a = j2 & 15;
            const int y = c_YD[a];
            const float* w = vw_mv + (c * 16) * 9;
            #pragma unroll
            for (int ci = 0; ci < 16; ci++) val += w[ci * 9 + y] * smv[ci][a];
            const int src = c_SRC[a];
            if (src >= 0) {
                const int y2 = c_Y2[a];
                #pragma unroll
                for (int ci = 0; ci < 16; ci++) val += w[ci * 9 + y2] * smv[ci][src];
            }
            if (a == 0) {
                #pragma unroll
                for (int i = 0; i < 32; i++) val += ss[i] * vw_s2mv[c * 32 + i];
                val += vb_mv[c];
            }
            g_vfeat[b][n][j2] = val;
        } else if (j < 448) {                // v scalars
            const int cs = j - 416;
            #pragma unroll
            for (int ci = 0; ci < 16; ci++) val += smv[ci][0] * vw_mv2s[cs * 16 + ci];
            #pragma unroll
            for (int i = 0; i < 32; i++) val += ss[i] * vw_s2s[cs * 32 + i];
            g_vfeat[b][n][256 + cs] = val + vb_s[cs];
        } else {                             // pad 288..319
            g_vfeat[b][n][j - 448 + 288] = 0.f;
        }
    }
}

// ================= Q projection =================
// q_feat[b][h][q][c*8+xi] = q_mv_out[channel c*8+h][INNER[xi]];  [128+cs] = q_s_out[cs*8+h]
__global__ __launch_bounds__(256) void q_proj_kernel(
    const float* __restrict__ mv_q, const float* __restrict__ s_q,
    const float* __restrict__ qw_mv, const float* __restrict__ qw_s2mv, const float* __restrict__ qb_mv,
    const float* __restrict__ qw_mv2s, const float* __restrict__ qw_s2s, const float* __restrict__ qb_s)
{
    const int tok = blockIdx.x;
    const int b = tok / NQ, q = tok % NQ;
    __shared__ float smv[16][16];
    __shared__ float ss[32];
    const int tid = threadIdx.x;
    ((float*)smv)[tid] = mv_q[(size_t)tok * 256 + tid];
    if (tid < 32) ss[tid] = s_q[(size_t)tok * 32 + tid];
    __syncthreads();

    for (int u = tid; u < NH * DQK; u += 256) {
        const int h = u / DQK, j = u % DQK;
        float val = 0.f;
        if (j < 128) {
            const int c = j >> 3, xi = j & 7;
            const int o = c * NH + h;
            const int a = c_INNER[xi], y = c_YD[a];
            const float* w = qw_mv + (o * 16) * 9 + y;
            #pragma unroll
            for (int ci = 0; ci < 16; ci++) val += w[ci * 9] * smv[ci][a];
            if (a == 0) {
                #pragma unroll
                for (int i = 0; i < 32; i++) val += ss[i] * qw_s2mv[o * 32 + i];
                val += qb_mv[o];
            }
        } else {
            const int cs = j - 128;
            const int os = cs * NH + h;
            #pragma unroll
            for (int ci = 0; ci < 16; ci++) val += smv[ci][0] * qw_mv2s[os * 16 + ci];
            #pragma unroll
            for (int i = 0; i < 32; i++) val += ss[i] * qw_s2s[os * 32 + i];
            val += qb_s[os];
        }
        g_qfeat[b][h][q][j] = val;
    }
}

// ================= Scores GEMM: S = scale * Q K^T =================
// 128x128 tile, BK=8, 256 threads, 8x8 microtile.
__global__ __launch_bounds__(256) void scores_kernel() {
    const int bh = blockIdx.z;
    const int b = bh >> 3, h = bh & 7;
    const float* __restrict__ A  = &g_qfeat[b][h][0][0];  // 2048 x 160
    const float* __restrict__ Bm = &g_kfeat[b][0][0];     // 2048 x 160
    float* __restrict__ C = &g_S[bh][0][0];
    const int m0 = blockIdx.y * 128;
    const int n0 = blockIdx.x * 128;
    __shared__ float As[8][132];
    __shared__ float Bs[8][132];
    const int tid = threadIdx.x;
    const int tx = tid & 15, ty = tid >> 4;
    const int lr = tid >> 1;
    const int lc = (tid & 1) << 2;
    float acc[8][8];
    #pragma unroll
    for (int i = 0; i < 8; i++)
        #pragma unroll
        for (int j = 0; j < 8; j++) acc[i][j] = 0.f;

    for (int k0 = 0; k0 < DQK; k0 += 8) {
        const float4 av = *(const float4*)(A  + (size_t)(m0 + lr) * DQK + (k0 + lc));
        const float4 bv = *(const float4*)(Bm + (size_t)(n0 + lr) * DQK + (k0 + lc));
        __syncthreads();
        As[lc + 0][lr] = av.x; As[lc + 1][lr] = av.y; As[lc + 2][lr] = av.z; As[lc + 3][lr] = av.w;
        Bs[lc + 0][lr] = bv.x; Bs[lc + 1][lr] = bv.y; Bs[lc + 2][lr] = bv.z; Bs[lc + 3][lr] = bv.w;
        __syncthreads();
        #pragma unroll
        for (int kk = 0; kk < 8; kk++) {
            float a[8], bb[8];
            *(float4*)&a[0]  = *(const float4*)&As[kk][ty * 8];
            *(float4*)&a[4]  = *(const float4*)&As[kk][ty * 8 + 4];
            *(float4*)&bb[0] = *(const float4*)&Bs[kk][tx * 8];
            *(float4*)&bb[4] = *(const float4*)&Bs[kk][tx * 8 + 4];
            #pragma unroll
            for (int i = 0; i < 8; i++)
                #pragma unroll
                for (int j = 0; j < 8; j++) acc[i][j] += a[i] * bb[j];
        }
    }
    #pragma unroll
    for (int i = 0; i < 8; i++) {
        const size_t row = m0 + ty * 8 + i;
        #pragma unroll
        for (int j = 0; j < 8; j += 4) {
            float4 v = make_float4(acc[i][j] * SCALE, acc[i][j + 1] * SCALE,
                                   acc[i][j + 2] * SCALE, acc[i][j + 3] * SCALE);
            *(float4*)(C + row * NKV + n0 + tx * 8 + j) = v;
        }
    }
}

// ================= Row softmax (in place) =================
__global__ __launch_bounds__(256) void softmax_kernel() {
    float* __restrict__ row = &g_S[0][0][0] + (size_t)blockIdx.x * NKV;
    const int tid = threadIdx.x;
    float4 x0 = *(float4*)(row + tid * 8);
    float4 x1 = *(float4*)(row + tid * 8 + 4);
    float m = fmaxf(fmaxf(fmaxf(x0.x, x0.y), fmaxf(x0.z, x0.w)),
                    fmaxf(fmaxf(x1.x, x1.y), fmaxf(x1.z, x1.w)));
    #pragma unroll
    for (int o = 16; o > 0; o >>= 1) m = fmaxf(m, __shfl_xor_sync(0xffffffffu, m, o));
    __shared__ float redm[8], reds[8];
    if ((tid & 31) == 0) redm[tid >> 5] = m;
    __syncthreads();
    float M = redm[0];
    #pragma unroll
    for (int i = 1; i < 8; i++) M = fmaxf(M, redm[i]);
    x0.x = __expf(x0.x - M); x0.y = __expf(x0.y - M); x0.z = __expf(x0.z - M); x0.w = __expf(x0.w - M);
    x1.x = __expf(x1.x - M); x1.y = __expf(x1.y - M); x1.z = __expf(x1.z - M); x1.w = __expf(x1.w - M);
    float s = x0.x + x0.y + x0.z + x0.w + x1.x + x1.y + x1.z + x1.w;
    #pragma unroll
    for (int o = 16; o > 0; o >>= 1) s += __shfl_xor_sync(0xffffffffu, s, o);
    if ((tid & 31) == 0) reds[tid >> 5] = s;
    __syncthreads();
    float S = 0.f;
    #pragma unroll
    for (int i = 0; i < 8; i++) S += reds[i];
    const float inv = 1.f / S;
    x0.x *= inv; x0.y *= inv; x0.z *= inv; x0.w *= inv;
    x1.x *= inv; x1.y *= inv; x1.z *= inv; x1.w *= inv;
    *(float4*)(row + tid * 8) = x0;
    *(float4*)(row + tid * 8 + 4) = x1;
}

// ================= PV GEMM: att = P V =================
// 128x64 tile, BK=16, 256 threads, 8x4 microtile.
__global__ __launch_bounds__(256) void pv_kernel() {
    const int bh = blockIdx.z;
    const int b = bh >> 3, h = bh & 7;
    const float* __restrict__ A  = &g_S[bh][0][0];     // 2048 x 2048 (probs)
    const float* __restrict__ Bm = &g_vfeat[b][0][0];  // 2048 x 320
    float* __restrict__ C = &g_att[b][h][0][0];        // 2048 x 320
    const int m0 = blockIdx.y * 128;
    const int n0 = blockIdx.x * 64;
    __shared__ float As[16][132];
    __shared__ float Bs[16][64];
    const int tid = threadIdx.x;
    const int tx = tid & 15, ty = tid >> 4;
    const int ar = tid >> 1;
    const int ac = (tid & 1) << 3;
    const int br = tid >> 4;
    const int bc = (tid & 15) << 2;
    float acc[8][4];
    #pragma unroll
    for (int i = 0; i < 8; i++)
        #pragma unroll
        for (int j = 0; j < 4; j++) acc[i][j] = 0.f;

    for (int k0 = 0; k0 < NKV; k0 += 16) {
        const float4 a0 = *(const float4*)(A + (size_t)(m0 + ar) * NKV + (k0 + ac));
        const float4 a1 = *(const float4*)(A + (size_t)(m0 + ar) * NKV + (k0 + ac + 4));
        const float4 bv = *(const float4*)(Bm + (size_t)(k0 + br) * DVP + (n0 + bc));
        __syncthreads();
        As[ac + 0][ar] = a0.x; As[ac + 1][ar] = a0.y; As[ac + 2][ar] = a0.z; As[ac + 3][ar] = a0.w;
        As[ac + 4][ar] = a1.x; As[ac + 5][ar] = a1.y; As[ac + 6][ar] = a1.z; As[ac + 7][ar] = a1.w;
        *(float4*)&Bs[br][bc] = bv;
        __syncthreads();
        #pragma unroll
        for (int kk = 0; kk < 16; kk++) {
            float a[8], bb[4];
            *(float4*)&a[0]  = *(const float4*)&As[kk][ty * 8];
            *(float4*)&a[4]  = *(const float4*)&As[kk][ty * 8 + 4];
            *(float4*)&bb[0] = *(const float4*)&Bs[kk][tx * 4];
            #pragma unroll
            for (int i = 0; i < 8; i++)
                #pragma unroll
                for (int j = 0; j < 4; j++) acc[i][j] += a[i] * bb[j];
        }
    }
    #pragma unroll
    for (int i = 0; i < 8; i++) {
        const size_t row = m0 + ty * 8 + i;
        *(float4*)(C + row * DVP + n0 + tx * 4) =
            make_float4(acc[i][0], acc[i][1], acc[i][2], acc[i][3]);
    }
}

// ================= O projection =================
// h_mv[c'=h*16+cm][a] = att[h][cm*16+a];  h_s[h*32+cs] = att[h][256+cs]
__global__ __launch_bounds__(256) void o_proj_kernel(
    float* __restrict__ out,
    const float* __restrict__ ow_mv, const float* __restrict__ ow_s2mv, const float* __restrict__ ob_mv,
    const float* __restrict__ ow_mv2s, const float* __restrict__ ow_s2s, const float* __restrict__ ob_s)
{
    const int tok = blockIdx.x;
    const int b = tok / NQ, q = tok % NQ;
    __shared__ float satt[NH * DV];  // 2304 floats
    const int tid = threadIdx.x;
    for (int u = tid; u < NH * DV; u += 256)
        satt[u] = g_att[b][u / DV][q][u % DV];
    __syncthreads();

    for (int u = tid; u < 288; u += 256) {
        float val = 0.f;
        if (u < 256) {                       // out_mv[o][a]
            const int o = u >> 4, a = u & 15;
            const int y = c_YD[a], y2 = c_Y2[a], src = c_SRC[a];
            if (src >= 0) {
                #pragma unroll 4
                for (int cp = 0; cp < 128; cp++) {
                    const float* w = ow_mv + (o * 128 + cp) * 9;
                    const int base = (cp >> 4) * DV + (cp & 15) * 16;
                    val += w[y]  * satt[base + a];
                    val += w[y2] * satt[base + src];
                }
            } else {
                #pragma unroll 4
                for (int cp = 0; cp < 128; cp++)
                    val += ow_mv[(o * 128 + cp) * 9 + y] * satt[(cp >> 4) * DV + (cp & 15) * 16 + a];
            }
            if (a == 0) {
                #pragma unroll 4
                for (int i = 0; i < 256; i++)
                    val += satt[(i >> 5) * DV + 256 + (i & 31)] * ow_s2mv[o * 256 + i];
                val += ob_mv[o];
            }
            out[(size_t)tok * 256 + o * 16 + a] = val;
        } else {                             // out_s[o]
            const int o = u - 256;
            #pragma unroll 4
            for (int cp = 0; cp < 128; cp++)
                val += satt[(cp >> 4) * DV + (cp & 15) * 16] * ow_mv2s[o * 128 + cp];
            #pragma unroll 4
            for (int i = 0; i < 256; i++)
                val += satt[(i >> 5) * DV + 256 + (i & 31)] * ow_s2s[o * 256 + i];
            out[(size_t)NB * NQ * 256 + (size_t)tok * 32 + o] = val + ob_s[o];
        }
    }
}

// ================= launch =================
extern "C" void kernel_launch(void* const* d_in, const int* in_sizes, int n_in,
                              void* d_out, int out_size)
{
    const float* mv_kv = (const float*)d_in[0];
    const float* mv_q  = (const float*)d_in[1];
    const float* s_kv  = (const float*)d_in[2];
    const float* s_q   = (const float*)d_in[3];
    const float* qw_mv   = (const float*)d_in[4];
    const float* qw_s2mv = (const float*)d_in[5];
    const float* qb_mv   = (const float*)d_in[6];
    const float* qw_mv2s = (const float*)d_in[7];
    const float* qw_s2s  = (const float*)d_in[8];
    const float* qb_s    = (const float*)d_in[9];
    const float* kw_mv   = (const float*)d_in[10];
    const float* kw_s2mv = (const float*)d_in[11];
    const float* kb_mv   = (const float*)d_in[12];
    const float* kw_mv2s = (const float*)d_in[13];
    const float* kw_s2s  = (const float*)d_in[14];
    const float* kb_s    = (const float*)d_in[15];
    const float* vw_mv   = (const float*)d_in[16];
    const float* vw_s2mv = (const float*)d_in[17];
    const float* vb_mv   = (const float*)d_in[18];
    const float* vw_mv2s = (const float*)d_in[19];
    const float* vw_s2s  = (const float*)d_in[20];
    const float* vb_s    = (const float*)d_in[21];
    const float* ow_mv   = (const float*)d_in[22];
    const float* ow_s2mv = (const float*)d_in[23];
    const float* ob_mv   = (const float*)d_in[24];
    const float* ow_mv2s = (const float*)d_in[25];
    const float* ow_s2s  = (const float*)d_in[26];
    const float* ob_s    = (const float*)d_in[27];
    float* out = (float*)d_out;

    kv_proj_kernel<<<NB * NKV, 256>>>(mv_kv, s_kv,
        kw_mv, kw_s2mv, kb_mv, kw_mv2s, kw_s2s, kb_s,
        vw_mv, vw_s2mv, vb_mv, vw_mv2s, vw_s2s, vb_s);
    q_proj_kernel<<<NB * NQ, 256>>>(mv_q, s_q,
        qw_mv, qw_s2mv, qb_mv, qw_mv2s, qw_s2s, qb_s);
    scores_kernel<<<dim3(NKV / 128, NQ / 128, NB * NH), 256>>>();
    softmax_kernel<<<NB * NH * NQ, 256>>>();
    pv_kernel<<<dim3(DVP / 64, NQ / 128, NB * NH), 256>>>();
    o_proj_kernel<<<NB * NQ, 256>>>(out,
        ow_mv, ow_s2mv, ob_mv, ow_mv2s, ow_s2s, ob_s);
}